// round 15
// baseline (speedup 1.0000x reference)
#include <cuda_runtime.h>
#include <cuda_bf16.h>

// Shapes fixed by the problem definition.
#define BATCH    256
#define HWPIX    1024           // 32*32
#define CHAN     256
#define NPART    4
#define PSIZE    64             // BATCH / NPART
#define EPSV     0.001f
#define NUNITS   4096u          // 64-pixel CTA units (both phases)
#define UNIT_PIX 64
#define NGROUP   16             // 4-row groups per unit
#define NSTASH   7              // groups stashed in DYNAMIC smem (28 KB)
#define CPS      4              // CTAs per SM (64 regs, high MLP -- proven)

// Scratch (allocation-free rule): device globals. All counters/accumulators
// are returned to zero by in-kernel handshakes before the kernel retires ->
// every graph replay sees identical initial state (deterministic).
__device__ float    g_sum[NPART][CHAN];
__device__ float    g_sq [NPART][CHAN];
__device__ unsigned g_tk1;    // phase-1 ticket   (reset by barrier master)
__device__ unsigned g_tk2;    // phase-2 ticket   (reset by last finisher)
__device__ unsigned g_cnt1;   // barrier arrivals (reset by barrier master)
__device__ unsigned g_rel1;   // barrier release epoch (monotonic)
__device__ unsigned g_fc;     // fold-consumed counter (reset by its last)
__device__ unsigned g_done;   // phase-2 finishers (reset by last finisher)

// ---------------------------------------------------------------------------
// One persistent kernel: stats -> grid barrier -> fold -> normalize.
// R13 design (best measured): pipelined CTA tickets (ONE sync per unit),
// double-buffered reductions, reversed phase 2 for the single L2 reuse
// window, cross-barrier smem stash of each CTA's LAST phase-1 unit which is
// normalized FIRST in phase 2. Change vs R13: stash lives in dynamic smem
// and covers 7/16 groups (28 KB) instead of 5/16 -> ~5 MB less DRAM reads.
// ---------------------------------------------------------------------------
__global__ void __launch_bounds__(256, CPS)
k_fused(const float4* __restrict__ x, float4* __restrict__ out,
        const float* __restrict__ gamma, const float* __restrict__ beta,
        const int* __restrict__ perm) {
    const int      t    = threadIdx.x;
    const int      c4   = t & 63;
    const int      psub = t >> 6;
    const unsigned nCTA = gridDim.x;
    const unsigned bid  = blockIdx.x;
    const unsigned NDYN = NUNITS - nCTA;   // dynamic units; last nCTA static

    __shared__ int      spart[BATCH];      // partition of each batch index
    __shared__ float    ssum[2][4][CHAN];  // double-buffered reduction arrays
    __shared__ float    ssq [2][4][CHAN];
    __shared__ float    sscale[NPART][CHAN];
    __shared__ float    sbias [NPART][CHAN];
    __shared__ unsigned stk[2];            // double-buffered ticket broadcast
    __shared__ int      slast;
    extern __shared__ float4 stash[];      // [NSTASH][256] cross-barrier stash

    // Build partition map per-CTA: position of b in perm, / 64.
    spart[perm[t]] = t >> 6;               // t / PSIZE

    // ---------------- Phase 1: stats (pipelined CTA tickets) -------------
    if (t == 0) stk[0] = atomicAdd(&g_tk1, 1u);
    __syncthreads();                       // publish first ticket + spart
    for (unsigned it = 0; ; it++) {
        const unsigned u = stk[it & 1u];
        if (u >= NDYN) break;
        if (t == 0) stk[(it + 1u) & 1u] = atomicAdd(&g_tk1, 1u);  // prefetch

        const int b     = (int)(u >> 4);
        const int chunk = (int)(u & 15);
        const float4* base =
            x + ((size_t)b * HWPIX + (size_t)chunk * UNIT_PIX) * (CHAN / 4) + c4;

        float4 s = make_float4(0.f, 0.f, 0.f, 0.f);
        float4 q = make_float4(0.f, 0.f, 0.f, 0.f);
        #pragma unroll
        for (int i = 0; i < NGROUP; i++) {
            float4 v = base[(size_t)(i * 4 + psub) * (CHAN / 4)];
            s.x += v.x; s.y += v.y; s.z += v.z; s.w += v.w;
            q.x += v.x * v.x; q.y += v.y * v.y; q.z += v.z * v.z; q.w += v.w * v.w;
        }

        float (*su)[CHAN] = ssum[it & 1u];
        float (*sv)[CHAN] = ssq [it & 1u];
        const int cbase = c4 * 4;
        su[psub][cbase + 0] = s.x; su[psub][cbase + 1] = s.y;
        su[psub][cbase + 2] = s.z; su[psub][cbase + 3] = s.w;
        sv[psub][cbase + 0] = q.x; sv[psub][cbase + 1] = q.y;
        sv[psub][cbase + 2] = q.z; sv[psub][cbase + 3] = q.w;
        __syncthreads();     // single sync: next ticket visible + smem fenced

        const int p = spart[b];
        atomicAdd(&g_sum[p][t], su[0][t] + su[1][t] + su[2][t] + su[3][t]);
        atomicAdd(&g_sq[p][t],  sv[0][t] + sv[1][t] + sv[2][t] + sv[3][t]);
        // next iteration writes the OTHER buffer -> these reads are safe
    }
    __syncthreads();         // drain last dynamic unit's reduction reads

    // ---- Static stash unit: us = NDYN + bid (this CTA's last p1 unit) ----
    {
        const unsigned us = NDYN + bid;
        const int b     = (int)(us >> 4);
        const int chunk = (int)(us & 15);
        const float4* base =
            x + ((size_t)b * HWPIX + (size_t)chunk * UNIT_PIX) * (CHAN / 4) + c4;

        float4 s = make_float4(0.f, 0.f, 0.f, 0.f);
        float4 q = make_float4(0.f, 0.f, 0.f, 0.f);
        #pragma unroll
        for (int i = 0; i < NGROUP; i++) {
            float4 v = base[(size_t)(i * 4 + psub) * (CHAN / 4)];
            if (i < NSTASH) stash[i * 256 + t] = v;   // keep for phase 2
            s.x += v.x; s.y += v.y; s.z += v.z; s.w += v.w;
            q.x += v.x * v.x; q.y += v.y * v.y; q.z += v.z * v.z; q.w += v.w * v.w;
        }

        const int cbase = c4 * 4;
        ssum[0][psub][cbase + 0] = s.x; ssum[0][psub][cbase + 1] = s.y;
        ssum[0][psub][cbase + 2] = s.z; ssum[0][psub][cbase + 3] = s.w;
        ssq [0][psub][cbase + 0] = q.x; ssq [0][psub][cbase + 1] = q.y;
        ssq [0][psub][cbase + 2] = q.z; ssq [0][psub][cbase + 3] = q.w;
        __syncthreads();

        const int p = spart[b];
        atomicAdd(&g_sum[p][t], ssum[0][0][t] + ssum[0][1][t] + ssum[0][2][t] + ssum[0][3][t]);
        atomicAdd(&g_sq[p][t],  ssq [0][0][t] + ssq [0][1][t] + ssq [0][2][t] + ssq [0][3][t]);
    }

    // ---------------- Grid barrier (all atomics visible) -----------------
    __syncthreads();
    if (t == 0) {
        __threadfence();
        unsigned r0  = atomicAdd(&g_rel1, 0u);        // epoch before arriving
        unsigned old = atomicAdd(&g_cnt1, 1u);
        if (old == nCTA - 1u) {                       // master: everyone done
            atomicExch(&g_cnt1, 0u);                  // reset for next replay
            atomicExch(&g_tk1, 0u);
            __threadfence();
            atomicAdd(&g_rel1, 1u);                   // release
        } else {
            while (atomicAdd(&g_rel1, 0u) == r0) { __nanosleep(64); }
        }
        __threadfence();
    }
    __syncthreads();

    // -------- Fold stats into fused scale/bias in shared (once/CTA) ------
    {
        const float invN = 1.0f / (float)(PSIZE * HWPIX);
        const float* sm = &g_sum[0][0];
        const float* sq = &g_sq[0][0];
        float* sc = &sscale[0][0];
        float* sb = &sbias[0][0];
        #pragma unroll
        for (int i = t; i < NPART * CHAN; i += 256) {
            float mean = sm[i] * invN;
            float var  = sq[i] * invN - mean * mean;
            float s    = gamma[i] * rsqrtf(var + EPSV);
            sc[i] = s;
            sb[i] = beta[i] - mean * s;
        }
        __syncthreads();
        // Last CTA to consume the accumulators re-zeroes them.
        if (t == 0) slast = (atomicAdd(&g_fc, 1u) == nCTA - 1u) ? 1 : 0;
        __syncthreads();
        if (slast) {
            float* gs = &g_sum[0][0];
            float* gq = &g_sq[0][0];
            #pragma unroll
            for (int i = t; i < NPART * CHAN; i += 256) { gs[i] = 0.f; gq[i] = 0.f; }
            __threadfence();
            if (t == 0) atomicExch(&g_fc, 0u);
        }
    }

    // ---- Phase 2 opener: normalize the stash unit (smem + hot L2) -------
    {
        const unsigned us = NDYN + bid;
        const int b     = (int)(us >> 4);
        const int chunk = (int)(us & 15);
        const int p     = spart[b];

        const float4 sc = *(const float4*)&sscale[p][c4 * 4];
        const float4 bi = *(const float4*)&sbias[p][c4 * 4];

        const size_t base =
            ((size_t)b * HWPIX + (size_t)chunk * UNIT_PIX) * (CHAN / 4) + c4;
        #pragma unroll
        for (int i = 0; i < NGROUP; i++) {
            size_t idx = base + (size_t)(i * 4 + psub) * (CHAN / 4);
            float4 v = (i < NSTASH) ? stash[i * 256 + t] : x[idx];
            v.x = v.x * sc.x + bi.x;
            v.y = v.y * sc.y + bi.y;
            v.z = v.z * sc.z + bi.z;
            v.w = v.w * sc.w + bi.w;
            out[idx] = v;
        }
    }

    // ------- Phase 2: normalize (pipelined CTA tickets, REVERSED) --------
    if (t == 0) stk[0] = atomicAdd(&g_tk2, 1u);
    __syncthreads();
    for (unsigned it = 0; ; it++) {
        const unsigned tk = stk[it & 1u];
        if (tk >= NDYN) break;
        if (t == 0) stk[(it + 1u) & 1u] = atomicAdd(&g_tk2, 1u);  // prefetch
        const unsigned u = NDYN - 1u - tk;            // newest-read units first

        const int b     = (int)(u >> 4);
        const int chunk = (int)(u & 15);
        const int p     = spart[b];

        const float4 sc = *(const float4*)&sscale[p][c4 * 4];
        const float4 bi = *(const float4*)&sbias[p][c4 * 4];

        const size_t base =
            ((size_t)b * HWPIX + (size_t)chunk * UNIT_PIX) * (CHAN / 4) + c4;
        #pragma unroll
        for (int i = 0; i < NGROUP; i++) {
            size_t idx = base + (size_t)(i * 4 + psub) * (CHAN / 4);
            float4 v = x[idx];
            v.x = v.x * sc.x + bi.x;
            v.y = v.y * sc.y + bi.y;
            v.z = v.z * sc.z + bi.z;
            v.w = v.w * sc.w + bi.w;
            out[idx] = v;
        }
        __syncthreads();     // single sync: publish the prefetched ticket
    }

    // ---------------- Exit handshake: reset tickets for next replay ------
    __syncthreads();
    if (t == 0) slast = (atomicAdd(&g_done, 1u) == nCTA - 1u) ? 1 : 0;
    __syncthreads();
    if (slast && t == 0) {
        atomicExch(&g_tk2, 0u);
        __threadfence();
        atomicExch(&g_done, 0u);
    }
}

// ---------------------------------------------------------------------------
extern "C" void kernel_launch(void* const* d_in, const int* in_sizes, int n_in,
                              void* d_out, int out_size) {
    const float* x     = (const float*)d_in[0];
    const float* gamma = (const float*)d_in[1];
    const float* beta  = (const float*)d_in[2];
    const int*   perm  = (const int*)d_in[3];

    int nsm = 0;
    cudaDeviceGetAttribute(&nsm, cudaDevAttrMultiProcessorCount, 0);
    if (nsm <= 0) nsm = 148;                 // defensive fallback
    const int grid = CPS * nsm;              // __launch_bounds__ => all resident
    const int dyn  = NSTASH * 256 * (int)sizeof(float4);   // 28 KB stash

    // Host-side attribute set (idempotent, not a stream op -> capture-safe).
    cudaFuncSetAttribute(k_fused, cudaFuncAttributeMaxDynamicSharedMemorySize, dyn);

    k_fused<<<grid, 256, dyn>>>((const float4*)x, (float4*)d_out, gamma, beta, perm);
}

// round 16
// speedup vs baseline: 1.1594x; 1.1594x over previous
#include <cuda_runtime.h>
#include <cuda_bf16.h>

// Shapes fixed by the problem definition.
#define BATCH    256
#define HWPIX    1024           // 32*32
#define CHAN     256
#define NPART    4
#define PSIZE    64             // BATCH / NPART
#define EPSV     0.001f
#define NUNITS   4096u          // 64-pixel CTA units (both phases)
#define UNIT_PIX 64
#define NGROUP   16             // 4-row groups per unit
#define NSTASH   5              // groups stashed in smem across the barrier
#define CPS      4              // CTAs per SM (64 regs, high MLP -- proven)

// Scratch (allocation-free rule): device globals. All counters/accumulators
// are returned to zero by in-kernel handshakes before the kernel retires ->
// every graph replay sees identical initial state (deterministic).
__device__ float    g_sum[NPART][CHAN];
__device__ float    g_sq [NPART][CHAN];
__device__ unsigned g_tk1;    // phase-1 ticket   (reset by barrier master)
__device__ unsigned g_tk2;    // phase-2 ticket   (reset by last finisher)
__device__ unsigned g_cnt1;   // barrier arrivals (reset by barrier master)
__device__ unsigned g_rel1;   // barrier release epoch (monotonic)
__device__ unsigned g_fc;     // fold-consumed counter (reset by its last)
__device__ unsigned g_done;   // phase-2 finishers (reset by last finisher)

// ---------------------------------------------------------------------------
// One persistent kernel: stats -> grid barrier -> fold -> normalize.
// Converged configuration (R13, best measured 123.4us wall):
//  * pipelined CTA tickets: next ticket atomic issued before current unit's
//    work, ONE __syncthreads per unit; double-buffered reduction arrays.
//  * reversed phase-2 order: newest-read x first -> ~63 MB L2 reuse.
//  * cross-barrier stash: each CTA statically owns unit NDYN+bid as its LAST
//    phase-1 unit, keeps 5/16 of it (20 KB static smem) and normalizes it
//    FIRST in phase 2 (stash + hot L2, no ticket stall).
//  * smem/CTA = 46 KB (smem/SM 184 KB) -- leaves 44 KB L1D; going beyond
//    this measurably throttles the load path (R15: 216 KB smem -> -15%).
// ---------------------------------------------------------------------------
__global__ void __launch_bounds__(256, CPS)
k_fused(const float4* __restrict__ x, float4* __restrict__ out,
        const float* __restrict__ gamma, const float* __restrict__ beta,
        const int* __restrict__ perm) {
    const int      t    = threadIdx.x;
    const int      c4   = t & 63;
    const int      psub = t >> 6;
    const unsigned nCTA = gridDim.x;
    const unsigned bid  = blockIdx.x;
    const unsigned NDYN = NUNITS - nCTA;   // dynamic units; last nCTA static

    __shared__ int      spart[BATCH];      // partition of each batch index
    __shared__ float    ssum[2][4][CHAN];  // double-buffered reduction arrays
    __shared__ float    ssq [2][4][CHAN];
    __shared__ float    sscale[NPART][CHAN];
    __shared__ float    sbias [NPART][CHAN];
    __shared__ float4   stash[NSTASH][256];  // 20 KB cross-barrier x stash
    __shared__ unsigned stk[2];            // double-buffered ticket broadcast
    __shared__ int      slast;

    // Build partition map per-CTA: position of b in perm, / 64.
    spart[perm[t]] = t >> 6;               // t / PSIZE

    // ---------------- Phase 1: stats (pipelined CTA tickets) -------------
    if (t == 0) stk[0] = atomicAdd(&g_tk1, 1u);
    __syncthreads();                       // publish first ticket + spart
    for (unsigned it = 0; ; it++) {
        const unsigned u = stk[it & 1u];
        if (u >= NDYN) break;
        if (t == 0) stk[(it + 1u) & 1u] = atomicAdd(&g_tk1, 1u);  // prefetch

        const int b     = (int)(u >> 4);
        const int chunk = (int)(u & 15);
        const float4* base =
            x + ((size_t)b * HWPIX + (size_t)chunk * UNIT_PIX) * (CHAN / 4) + c4;

        float4 s = make_float4(0.f, 0.f, 0.f, 0.f);
        float4 q = make_float4(0.f, 0.f, 0.f, 0.f);
        #pragma unroll
        for (int i = 0; i < NGROUP; i++) {
            float4 v = base[(size_t)(i * 4 + psub) * (CHAN / 4)];
            s.x += v.x; s.y += v.y; s.z += v.z; s.w += v.w;
            q.x += v.x * v.x; q.y += v.y * v.y; q.z += v.z * v.z; q.w += v.w * v.w;
        }

        float (*su)[CHAN] = ssum[it & 1u];
        float (*sv)[CHAN] = ssq [it & 1u];
        const int cbase = c4 * 4;
        su[psub][cbase + 0] = s.x; su[psub][cbase + 1] = s.y;
        su[psub][cbase + 2] = s.z; su[psub][cbase + 3] = s.w;
        sv[psub][cbase + 0] = q.x; sv[psub][cbase + 1] = q.y;
        sv[psub][cbase + 2] = q.z; sv[psub][cbase + 3] = q.w;
        __syncthreads();     // single sync: next ticket visible + smem fenced

        const int p = spart[b];
        atomicAdd(&g_sum[p][t], su[0][t] + su[1][t] + su[2][t] + su[3][t]);
        atomicAdd(&g_sq[p][t],  sv[0][t] + sv[1][t] + sv[2][t] + sv[3][t]);
        // next iteration writes the OTHER buffer -> these reads are safe
    }
    __syncthreads();         // drain last dynamic unit's reduction reads

    // ---- Static stash unit: us = NDYN + bid (this CTA's last p1 unit) ----
    {
        const unsigned us = NDYN + bid;
        const int b     = (int)(us >> 4);
        const int chunk = (int)(us & 15);
        const float4* base =
            x + ((size_t)b * HWPIX + (size_t)chunk * UNIT_PIX) * (CHAN / 4) + c4;

        float4 s = make_float4(0.f, 0.f, 0.f, 0.f);
        float4 q = make_float4(0.f, 0.f, 0.f, 0.f);
        #pragma unroll
        for (int i = 0; i < NGROUP; i++) {
            float4 v = base[(size_t)(i * 4 + psub) * (CHAN / 4)];
            if (i < NSTASH) stash[i][t] = v;   // keep for phase 2
            s.x += v.x; s.y += v.y; s.z += v.z; s.w += v.w;
            q.x += v.x * v.x; q.y += v.y * v.y; q.z += v.z * v.z; q.w += v.w * v.w;
        }

        const int cbase = c4 * 4;
        ssum[0][psub][cbase + 0] = s.x; ssum[0][psub][cbase + 1] = s.y;
        ssum[0][psub][cbase + 2] = s.z; ssum[0][psub][cbase + 3] = s.w;
        ssq [0][psub][cbase + 0] = q.x; ssq [0][psub][cbase + 1] = q.y;
        ssq [0][psub][cbase + 2] = q.z; ssq [0][psub][cbase + 3] = q.w;
        __syncthreads();

        const int p = spart[b];
        atomicAdd(&g_sum[p][t], ssum[0][0][t] + ssum[0][1][t] + ssum[0][2][t] + ssum[0][3][t]);
        atomicAdd(&g_sq[p][t],  ssq [0][0][t] + ssq [0][1][t] + ssq [0][2][t] + ssq [0][3][t]);
    }

    // ---------------- Grid barrier (all atomics visible) -----------------
    __syncthreads();
    if (t == 0) {
        __threadfence();
        unsigned r0  = atomicAdd(&g_rel1, 0u);        // epoch before arriving
        unsigned old = atomicAdd(&g_cnt1, 1u);
        if (old == nCTA - 1u) {                       // master: everyone done
            atomicExch(&g_cnt1, 0u);                  // reset for next replay
            atomicExch(&g_tk1, 0u);
            __threadfence();
            atomicAdd(&g_rel1, 1u);                   // release
        } else {
            while (atomicAdd(&g_rel1, 0u) == r0) { __nanosleep(64); }
        }
        __threadfence();
    }
    __syncthreads();

    // -------- Fold stats into fused scale/bias in shared (once/CTA) ------
    {
        const float invN = 1.0f / (float)(PSIZE * HWPIX);
        const float* sm = &g_sum[0][0];
        const float* sq = &g_sq[0][0];
        float* sc = &sscale[0][0];
        float* sb = &sbias[0][0];
        #pragma unroll
        for (int i = t; i < NPART * CHAN; i += 256) {
            float mean = sm[i] * invN;
            float var  = sq[i] * invN - mean * mean;
            float s    = gamma[i] * rsqrtf(var + EPSV);
            sc[i] = s;
            sb[i] = beta[i] - mean * s;
        }
        __syncthreads();
        // Last CTA to consume the accumulators re-zeroes them.
        if (t == 0) slast = (atomicAdd(&g_fc, 1u) == nCTA - 1u) ? 1 : 0;
        __syncthreads();
        if (slast) {
            float* gs = &g_sum[0][0];
            float* gq = &g_sq[0][0];
            #pragma unroll
            for (int i = t; i < NPART * CHAN; i += 256) { gs[i] = 0.f; gq[i] = 0.f; }
            __threadfence();
            if (t == 0) atomicExch(&g_fc, 0u);
        }
    }

    // ---- Phase 2 opener: normalize the stash unit (smem + hot L2) -------
    {
        const unsigned us = NDYN + bid;
        const int b     = (int)(us >> 4);
        const int chunk = (int)(us & 15);
        const int p     = spart[b];

        const float4 sc = *(const float4*)&sscale[p][c4 * 4];
        const float4 bi = *(const float4*)&sbias[p][c4 * 4];

        const size_t base =
            ((size_t)b * HWPIX + (size_t)chunk * UNIT_PIX) * (CHAN / 4) + c4;
        #pragma unroll
        for (int i = 0; i < NGROUP; i++) {
            size_t idx = base + (size_t)(i * 4 + psub) * (CHAN / 4);
            float4 v = (i < NSTASH) ? stash[i][t] : x[idx];
            v.x = v.x * sc.x + bi.x;
            v.y = v.y * sc.y + bi.y;
            v.z = v.z * sc.z + bi.z;
            v.w = v.w * sc.w + bi.w;
            out[idx] = v;
        }
    }

    // ------- Phase 2: normalize (pipelined CTA tickets, REVERSED) --------
    if (t == 0) stk[0] = atomicAdd(&g_tk2, 1u);
    __syncthreads();
    for (unsigned it = 0; ; it++) {
        const unsigned tk = stk[it & 1u];
        if (tk >= NDYN) break;
        if (t == 0) stk[(it + 1u) & 1u] = atomicAdd(&g_tk2, 1u);  // prefetch
        const unsigned u = NDYN - 1u - tk;            // newest-read units first

        const int b     = (int)(u >> 4);
        const int chunk = (int)(u & 15);
        const int p     = spart[b];

        const float4 sc = *(const float4*)&sscale[p][c4 * 4];
        const float4 bi = *(const float4*)&sbias[p][c4 * 4];

        const size_t base =
            ((size_t)b * HWPIX + (size_t)chunk * UNIT_PIX) * (CHAN / 4) + c4;
        #pragma unroll
        for (int i = 0; i < NGROUP; i++) {
            size_t idx = base + (size_t)(i * 4 + psub) * (CHAN / 4);
            float4 v = x[idx];
            v.x = v.x * sc.x + bi.x;
            v.y = v.y * sc.y + bi.y;
            v.z = v.z * sc.z + bi.z;
            v.w = v.w * sc.w + bi.w;
            out[idx] = v;
        }
        __syncthreads();     // single sync: publish the prefetched ticket
    }

    // ---------------- Exit handshake: reset tickets for next replay ------
    __syncthreads();
    if (t == 0) slast = (atomicAdd(&g_done, 1u) == nCTA - 1u) ? 1 : 0;
    __syncthreads();
    if (slast && t == 0) {
        atomicExch(&g_tk2, 0u);
        __threadfence();
        atomicExch(&g_done, 0u);
    }
}

// ---------------------------------------------------------------------------
extern "C" void kernel_launch(void* const* d_in, const int* in_sizes, int n_in,
                              void* d_out, int out_size) {
    const float* x     = (const float*)d_in[0];
    const float* gamma = (const float*)d_in[1];
    const float* beta  = (const float*)d_in[2];
    const int*   perm  = (const int*)d_in[3];

    int nsm = 0;
    cudaDeviceGetAttribute(&nsm, cudaDevAttrMultiProcessorCount, 0);
    if (nsm <= 0) nsm = 148;                 // defensive fallback
    const int grid = CPS * nsm;              // __launch_bounds__ => all resident

    k_fused<<<grid, 256>>>((const float4*)x, (float4*)d_out, gamma, beta, perm);
}

// round 17
// speedup vs baseline: 1.1737x; 1.0123x over previous
#include <cuda_runtime.h>
#include <cuda_bf16.h>

// Shapes fixed by the problem definition.
#define BATCH    256
#define HWPIX    1024           // 32*32
#define CHAN     256
#define NPART    4
#define PSIZE    64             // BATCH / NPART
#define EPSV     0.001f
#define NUNITS   4096u          // 64-pixel phase-1 units
#define UNIT_PIX 64
#define NGROUP   16             // 4-row groups per 64px unit
#define NSTASH   5              // groups stashed in smem across the barrier
#define CPS      4              // CTAs per SM (64 regs, high MLP -- proven)
// Phase 2 uses 32-pixel units over the dynamic region (finer end-taper).
#define U2_PIX   32
#define NG2      8              // 4-row groups per 32px unit

// Scratch (allocation-free rule): device globals. All counters/accumulators
// are returned to zero by in-kernel handshakes before the kernel retires ->
// every graph replay sees identical initial state (deterministic).
__device__ float    g_sum[NPART][CHAN];
__device__ float    g_sq [NPART][CHAN];
__device__ unsigned g_tk1;    // phase-1 ticket   (reset by barrier master)
__device__ unsigned g_tk2;    // phase-2 ticket   (reset by last finisher)
__device__ unsigned g_cnt1;   // barrier arrivals (reset by barrier master)
__device__ unsigned g_rel1;   // barrier release epoch (monotonic)
__device__ unsigned g_fc;     // fold-consumed counter (reset by its last)
__device__ unsigned g_done;   // phase-2 finishers (reset by last finisher)

// ---------------------------------------------------------------------------
// One persistent kernel: stats -> grid barrier -> fold -> normalize.
// R13/R16 converged skeleton (pipelined CTA tickets, ONE sync per unit,
// double-buffered reductions, reversed phase 2, 20 KB cross-barrier stash,
// smem/SM = 184 KB to preserve 44 KB L1D). Single change: phase-2 dynamic
// units are 32 pixels (2x ticket count) -- halves the end-of-kernel taper
// (a 64px unit is ~6.7us of traffic) at ~0.3us extra sync/ticket cost.
// ---------------------------------------------------------------------------
__global__ void __launch_bounds__(256, CPS)
k_fused(const float4* __restrict__ x, float4* __restrict__ out,
        const float* __restrict__ gamma, const float* __restrict__ beta,
        const int* __restrict__ perm) {
    const int      t    = threadIdx.x;
    const int      c4   = t & 63;
    const int      psub = t >> 6;
    const unsigned nCTA = gridDim.x;
    const unsigned bid  = blockIdx.x;
    const unsigned NDYN = NUNITS - nCTA;   // dynamic 64px units; last nCTA static
    const unsigned ND2  = NDYN * 2u;       // dynamic region in 32px units

    __shared__ int      spart[BATCH];      // partition of each batch index
    __shared__ float    ssum[2][4][CHAN];  // double-buffered reduction arrays
    __shared__ float    ssq [2][4][CHAN];
    __shared__ float    sscale[NPART][CHAN];
    __shared__ float    sbias [NPART][CHAN];
    __shared__ float4   stash[NSTASH][256];  // 20 KB cross-barrier x stash
    __shared__ unsigned stk[2];            // double-buffered ticket broadcast
    __shared__ int      slast;

    // Build partition map per-CTA: position of b in perm, / 64.
    spart[perm[t]] = t >> 6;               // t / PSIZE

    // ---------------- Phase 1: stats (pipelined CTA tickets, 64px) -------
    if (t == 0) stk[0] = atomicAdd(&g_tk1, 1u);
    __syncthreads();                       // publish first ticket + spart
    for (unsigned it = 0; ; it++) {
        const unsigned u = stk[it & 1u];
        if (u >= NDYN) break;
        if (t == 0) stk[(it + 1u) & 1u] = atomicAdd(&g_tk1, 1u);  // prefetch

        const int b     = (int)(u >> 4);
        const int chunk = (int)(u & 15);
        const float4* base =
            x + ((size_t)b * HWPIX + (size_t)chunk * UNIT_PIX) * (CHAN / 4) + c4;

        float4 s = make_float4(0.f, 0.f, 0.f, 0.f);
        float4 q = make_float4(0.f, 0.f, 0.f, 0.f);
        #pragma unroll
        for (int i = 0; i < NGROUP; i++) {
            float4 v = base[(size_t)(i * 4 + psub) * (CHAN / 4)];
            s.x += v.x; s.y += v.y; s.z += v.z; s.w += v.w;
            q.x += v.x * v.x; q.y += v.y * v.y; q.z += v.z * v.z; q.w += v.w * v.w;
        }

        float (*su)[CHAN] = ssum[it & 1u];
        float (*sv)[CHAN] = ssq [it & 1u];
        const int cbase = c4 * 4;
        su[psub][cbase + 0] = s.x; su[psub][cbase + 1] = s.y;
        su[psub][cbase + 2] = s.z; su[psub][cbase + 3] = s.w;
        sv[psub][cbase + 0] = q.x; sv[psub][cbase + 1] = q.y;
        sv[psub][cbase + 2] = q.z; sv[psub][cbase + 3] = q.w;
        __syncthreads();     // single sync: next ticket visible + smem fenced

        const int p = spart[b];
        atomicAdd(&g_sum[p][t], su[0][t] + su[1][t] + su[2][t] + su[3][t]);
        atomicAdd(&g_sq[p][t],  sv[0][t] + sv[1][t] + sv[2][t] + sv[3][t]);
        // next iteration writes the OTHER buffer -> these reads are safe
    }
    __syncthreads();         // drain last dynamic unit's reduction reads

    // ---- Static stash unit: us = NDYN + bid (this CTA's last p1 unit) ----
    {
        const unsigned us = NDYN + bid;
        const int b     = (int)(us >> 4);
        const int chunk = (int)(us & 15);
        const float4* base =
            x + ((size_t)b * HWPIX + (size_t)chunk * UNIT_PIX) * (CHAN / 4) + c4;

        float4 s = make_float4(0.f, 0.f, 0.f, 0.f);
        float4 q = make_float4(0.f, 0.f, 0.f, 0.f);
        #pragma unroll
        for (int i = 0; i < NGROUP; i++) {
            float4 v = base[(size_t)(i * 4 + psub) * (CHAN / 4)];
            if (i < NSTASH) stash[i][t] = v;   // keep for phase 2
            s.x += v.x; s.y += v.y; s.z += v.z; s.w += v.w;
            q.x += v.x * v.x; q.y += v.y * v.y; q.z += v.z * v.z; q.w += v.w * v.w;
        }

        const int cbase = c4 * 4;
        ssum[0][psub][cbase + 0] = s.x; ssum[0][psub][cbase + 1] = s.y;
        ssum[0][psub][cbase + 2] = s.z; ssum[0][psub][cbase + 3] = s.w;
        ssq [0][psub][cbase + 0] = q.x; ssq [0][psub][cbase + 1] = q.y;
        ssq [0][psub][cbase + 2] = q.z; ssq [0][psub][cbase + 3] = q.w;
        __syncthreads();

        const int p = spart[b];
        atomicAdd(&g_sum[p][t], ssum[0][0][t] + ssum[0][1][t] + ssum[0][2][t] + ssum[0][3][t]);
        atomicAdd(&g_sq[p][t],  ssq [0][0][t] + ssq [0][1][t] + ssq [0][2][t] + ssq [0][3][t]);
    }

    // ---------------- Grid barrier (all atomics visible) -----------------
    __syncthreads();
    if (t == 0) {
        __threadfence();
        unsigned r0  = atomicAdd(&g_rel1, 0u);        // epoch before arriving
        unsigned old = atomicAdd(&g_cnt1, 1u);
        if (old == nCTA - 1u) {                       // master: everyone done
            atomicExch(&g_cnt1, 0u);                  // reset for next replay
            atomicExch(&g_tk1, 0u);
            __threadfence();
            atomicAdd(&g_rel1, 1u);                   // release
        } else {
            while (atomicAdd(&g_rel1, 0u) == r0) { __nanosleep(64); }
        }
        __threadfence();
    }
    __syncthreads();

    // -------- Fold stats into fused scale/bias in shared (once/CTA) ------
    {
        const float invN = 1.0f / (float)(PSIZE * HWPIX);
        const float* sm = &g_sum[0][0];
        const float* sq = &g_sq[0][0];
        float* sc = &sscale[0][0];
        float* sb = &sbias[0][0];
        #pragma unroll
        for (int i = t; i < NPART * CHAN; i += 256) {
            float mean = sm[i] * invN;
            float var  = sq[i] * invN - mean * mean;
            float s    = gamma[i] * rsqrtf(var + EPSV);
            sc[i] = s;
            sb[i] = beta[i] - mean * s;
        }
        __syncthreads();
        // Last CTA to consume the accumulators re-zeroes them.
        if (t == 0) slast = (atomicAdd(&g_fc, 1u) == nCTA - 1u) ? 1 : 0;
        __syncthreads();
        if (slast) {
            float* gs = &g_sum[0][0];
            float* gq = &g_sq[0][0];
            #pragma unroll
            for (int i = t; i < NPART * CHAN; i += 256) { gs[i] = 0.f; gq[i] = 0.f; }
            __threadfence();
            if (t == 0) atomicExch(&g_fc, 0u);
        }
    }

    // ---- Phase 2 opener: normalize the stash unit (smem + hot L2) -------
    {
        const unsigned us = NDYN + bid;
        const int b     = (int)(us >> 4);
        const int chunk = (int)(us & 15);
        const int p     = spart[b];

        const float4 sc = *(const float4*)&sscale[p][c4 * 4];
        const float4 bi = *(const float4*)&sbias[p][c4 * 4];

        const size_t base =
            ((size_t)b * HWPIX + (size_t)chunk * UNIT_PIX) * (CHAN / 4) + c4;
        #pragma unroll
        for (int i = 0; i < NGROUP; i++) {
            size_t idx = base + (size_t)(i * 4 + psub) * (CHAN / 4);
            float4 v = (i < NSTASH) ? stash[i][t] : x[idx];
            v.x = v.x * sc.x + bi.x;
            v.y = v.y * sc.y + bi.y;
            v.z = v.z * sc.z + bi.z;
            v.w = v.w * sc.w + bi.w;
            out[idx] = v;
        }
    }

    // --- Phase 2: normalize (pipelined CTA tickets, REVERSED, 32px) ------
    if (t == 0) stk[0] = atomicAdd(&g_tk2, 1u);
    __syncthreads();
    for (unsigned it = 0; ; it++) {
        const unsigned tk = stk[it & 1u];
        if (tk >= ND2) break;
        if (t == 0) stk[(it + 1u) & 1u] = atomicAdd(&g_tk2, 1u);  // prefetch
        const unsigned u = ND2 - 1u - tk;             // newest-read units first

        const int b     = (int)(u >> 5);              // 32 units per batch
        const int chunk = (int)(u & 31);
        const int p     = spart[b];

        const float4 sc = *(const float4*)&sscale[p][c4 * 4];
        const float4 bi = *(const float4*)&sbias[p][c4 * 4];

        const size_t base =
            ((size_t)b * HWPIX + (size_t)chunk * U2_PIX) * (CHAN / 4) + c4;
        #pragma unroll
        for (int i = 0; i < NG2; i++) {
            size_t idx = base + (size_t)(i * 4 + psub) * (CHAN / 4);
            float4 v = x[idx];
            v.x = v.x * sc.x + bi.x;
            v.y = v.y * sc.y + bi.y;
            v.z = v.z * sc.z + bi.z;
            v.w = v.w * sc.w + bi.w;
            out[idx] = v;
        }
        __syncthreads();     // single sync: publish the prefetched ticket
    }

    // ---------------- Exit handshake: reset tickets for next replay ------
    __syncthreads();
    if (t == 0) slast = (atomicAdd(&g_done, 1u) == nCTA - 1u) ? 1 : 0;
    __syncthreads();
    if (slast && t == 0) {
        atomicExch(&g_tk2, 0u);
        __threadfence();
        atomicExch(&g_done, 0u);
    }
}

// ---------------------------------------------------------------------------
extern "C" void kernel_launch(void* const* d_in, const int* in_sizes, int n_in,
                              void* d_out, int out_size) {
    const float* x     = (const float*)d_in[0];
    const float* gamma = (const float*)d_in[1];
    const float* beta  = (const float*)d_in[2];
    const int*   perm  = (const int*)d_in[3];

    int nsm = 0;
    cudaDeviceGetAttribute(&nsm, cudaDevAttrMultiProcessorCount, 0);
    if (nsm <= 0) nsm = 148;                 // defensive fallback
    const int grid = CPS * nsm;              // __launch_bounds__ => all resident

    k_fused<<<grid, 256>>>((const float4*)x, (float4*)d_out, gamma, beta, perm);
}